// round 11
// baseline (speedup 1.0000x reference)
#include <cuda_runtime.h>
#include <cstdint>

// LogicGatedSNN: spikes = (membrane + x · (states > 50)^T + noise) >= threshold
// x: [8192] fp32 binary, states: [8192, 8192] fp32, out: [8192] fp32
//
// DRAM-bound 256 MiB single-pass stream (R5 body: CTA-per-row, MLP=8 LDG.128,
// x as 1KiB bitmask). SINGLE kernel launch: block 0 packs x and release-stores
// a flag; all other CTAs front their states loads, then spin briefly on the
// flag (hidden under the DRAM fill) before reading the bitmask via __ldcg.
// Last CTA to finish resets flag+counter so every graph replay does identical
// work (no cross-call caching).

#define IN_F   8192
#define OUT_F  8192
#define NTHR   256
#define NWARPS (NTHR / 32)
#define VEC    (IN_F / 4 / NTHR)           // 8 float4 per thread

__device__ unsigned g_xbits[NTHR];          // packed x bitmask (1 KiB)
__device__ int g_flag = 0;                  // release flag: bitmask ready
__device__ int g_done = 0;                  // completion counter for reset

__global__ __launch_bounds__(NTHR) void snn_fused_kernel(
    const float* __restrict__ x,        // [IN_F]
    const float* __restrict__ states,   // [OUT_F, IN_F]
    const float* __restrict__ mem,      // [OUT_F]
    const float* __restrict__ thr,      // [OUT_F]
    const float* __restrict__ noise,    // [OUT_F]
    float* __restrict__ out)            // [OUT_F]
{
    __shared__ int wsum[NWARPS];

    const int tid = threadIdx.x;
    const int row = blockIdx.x;

    const float4* __restrict__ s4 =
        reinterpret_cast<const float4*>(states + (size_t)row * IN_F);

    // Front the states stream immediately: 8 independent LDG.128 per thread.
    float4 s[VEC];
    #pragma unroll
    for (int j = 0; j < VEC; ++j)
        s[j] = __ldcs(&s4[j * NTHR + tid]);

    unsigned X;
    if (row == 0) {
        // Block 0 packs x (states loads already in flight above).
        const float4* __restrict__ x4 = reinterpret_cast<const float4*>(x);
        unsigned w = 0;
        #pragma unroll
        for (int j = 0; j < VEC; ++j) {
            const float4 v = x4[j * NTHR + tid];
            unsigned nib = (v.x != 0.0f ? 1u : 0u)
                         | (v.y != 0.0f ? 2u : 0u)
                         | (v.z != 0.0f ? 4u : 0u)
                         | (v.w != 0.0f ? 8u : 0u);
            w |= nib << (4 * j);
        }
        g_xbits[tid] = w;
        __threadfence();                 // publish bitmask before flag
        __syncthreads();                 // all words written
        if (tid == 0)
            asm volatile("st.release.gpu.global.b32 [%0], %1;"
                         :: "l"(&g_flag), "r"(1) : "memory");
        X = w;                           // block 0 uses its own registers
    } else {
        // One thread waits for the bitmask; overlaps the load-scoreboard wait.
        if (tid == 0) {
            int f;
            do {
                asm volatile("ld.acquire.gpu.global.b32 %0, [%1];"
                             : "=r"(f) : "l"(&g_flag) : "memory");
                if (f) break;
                __nanosleep(64);
            } while (true);
        }
        __syncthreads();
        X = __ldcg(&g_xbits[tid]);       // L2 read, 1 KiB total, hot
    }

    int cnt = 0;
    #pragma unroll
    for (int j = 0; j < VEC; ++j) {
        const unsigned nib = X >> (4 * j);
        cnt += (s[j].x > 50.0f) & (int)(nib & 1u);
        cnt += (s[j].y > 50.0f) & (int)((nib >> 1) & 1u);
        cnt += (s[j].z > 50.0f) & (int)((nib >> 2) & 1u);
        cnt += (s[j].w > 50.0f) & (int)((nib >> 3) & 1u);
    }

    // Warp reduce (int)
    #pragma unroll
    for (int off = 16; off > 0; off >>= 1)
        cnt += __shfl_xor_sync(0xffffffffu, cnt, off);

    if ((tid & 31) == 0) wsum[tid >> 5] = cnt;
    __syncthreads();

    if (tid == 0) {
        int c = 0;
        #pragma unroll
        for (int w = 0; w < NWARPS; ++w)
            c += wsum[w];
        const float p = mem[row] + (float)c + noise[row];
        out[row] = (p >= thr[row]) ? 1.0f : 0.0f;

        // Reset protocol state on the last CTA so every replay is identical.
        __threadfence();
        const int d = atomicAdd(&g_done, 1);
        if (d == gridDim.x - 1) {
            g_flag = 0;
            g_done = 0;
            __threadfence();
        }
    }
}

extern "C" void kernel_launch(void* const* d_in, const int* in_sizes, int n_in,
                              void* d_out, int out_size) {
    const float* x      = (const float*)d_in[0];  // spike_input [1, 8192]
    const float* states = (const float*)d_in[1];  // synapse_states [8192, 8192]
    const float* mem    = (const float*)d_in[2];  // membrane_potential [8192]
    const float* thr    = (const float*)d_in[3];  // adaptive_threshold [8192]
    const float* noise  = (const float*)d_in[4];  // noise [8192]
    float* out = (float*)d_out;                   // spikes [8192]

    snn_fused_kernel<<<OUT_F, NTHR>>>(x, states, mem, thr, noise, out);
}

// round 12
// speedup vs baseline: 1.2421x; 1.2421x over previous
#include <cuda_runtime.h>
#include <cstdint>

// LogicGatedSNN: spikes = (membrane + x · (states > 50)^T + noise) >= threshold
// x: [8192] fp32 binary, states: [8192, 8192] fp32, out: [8192] fp32
//
// DRAM-bound 256 MiB single-pass stream. Converged structure (best of 7
// designs over 11 rounds): x packed once into a 1KiB bitmask by a tiny
// pre-kernel (removes 256MB of parasitic x re-read traffic); main kernel is
// CTA-per-row, 256 threads, 8 independent streaming LDG.128 per thread
// (64 warps/SM x MLP 8 = peak L1tex/DRAM duty). Tail: REDUX-free 5-shfl warp
// reduce + warp-0-parallel cross-warp sum (shorter serial tail than tid0 loop).
// PDL / persistent / fused-flag variants all measured slower.

#define IN_F   8192
#define OUT_F  8192
#define NTHR   256
#define NWARPS (NTHR / 32)
#define VEC    (IN_F / 4 / NTHR)           // 8 float4 per thread

// Packed x: word t holds bits for thread-slot t's 32 columns.
// bit (4*j + c) = x[4*(j*NTHR + t) + c] != 0
__device__ unsigned g_xbits[NTHR];

__global__ __launch_bounds__(NTHR) void pack_x_kernel(const float* __restrict__ x)
{
    const int tid = threadIdx.x;
    const float4* __restrict__ x4 = reinterpret_cast<const float4*>(x);
    unsigned w = 0;
    #pragma unroll
    for (int j = 0; j < VEC; ++j) {
        const float4 v = x4[j * NTHR + tid];
        unsigned nib = (v.x != 0.0f ? 1u : 0u)
                     | (v.y != 0.0f ? 2u : 0u)
                     | (v.z != 0.0f ? 4u : 0u)
                     | (v.w != 0.0f ? 8u : 0u);
        w |= nib << (4 * j);
    }
    g_xbits[tid] = w;
}

__global__ __launch_bounds__(NTHR) void snn_bits_kernel(
    const float* __restrict__ states,   // [OUT_F, IN_F]
    const float* __restrict__ mem,      // [OUT_F]
    const float* __restrict__ thr,      // [OUT_F]
    const float* __restrict__ noise,    // [OUT_F]
    float* __restrict__ out)            // [OUT_F]
{
    __shared__ int wsum[NWARPS];

    const int tid = threadIdx.x;
    const int row = blockIdx.x;

    const float4* __restrict__ s4 =
        reinterpret_cast<const float4*>(states + (size_t)row * IN_F);

    // states row: 8 independent streaming LDG.128 per thread, issued up front
    float4 s[VEC];
    #pragma unroll
    for (int j = 0; j < VEC; ++j)
        s[j] = __ldcs(&s4[j * NTHR + tid]);

    const unsigned X = g_xbits[tid];     // 1KiB total, L1-hot

    int cnt = 0;
    #pragma unroll
    for (int j = 0; j < VEC; ++j) {
        const unsigned nib = X >> (4 * j);
        cnt += (s[j].x > 50.0f) & (int)(nib & 1u);
        cnt += (s[j].y > 50.0f) & (int)((nib >> 1) & 1u);
        cnt += (s[j].z > 50.0f) & (int)((nib >> 2) & 1u);
        cnt += (s[j].w > 50.0f) & (int)((nib >> 3) & 1u);
    }

    // Warp reduce (int)
    #pragma unroll
    for (int off = 16; off > 0; off >>= 1)
        cnt += __shfl_xor_sync(0xffffffffu, cnt, off);

    if ((tid & 31) == 0) wsum[tid >> 5] = cnt;
    __syncthreads();

    // Cross-warp sum done in parallel by warp 0 (8 lanes + 3 shfls),
    // shorter serial tail than a tid0 loop over 8 LDS.
    if (tid < 32) {
        int c = (tid < NWARPS) ? wsum[tid] : 0;
        #pragma unroll
        for (int off = 4; off > 0; off >>= 1)
            c += __shfl_xor_sync(0xffffffffu, c, off);
        if (tid == 0) {
            const float p = mem[row] + (float)c + noise[row];
            out[row] = (p >= thr[row]) ? 1.0f : 0.0f;
        }
    }
}

extern "C" void kernel_launch(void* const* d_in, const int* in_sizes, int n_in,
                              void* d_out, int out_size) {
    const float* x      = (const float*)d_in[0];  // spike_input [1, 8192]
    const float* states = (const float*)d_in[1];  // synapse_states [8192, 8192]
    const float* mem    = (const float*)d_in[2];  // membrane_potential [8192]
    const float* thr    = (const float*)d_in[3];  // adaptive_threshold [8192]
    const float* noise  = (const float*)d_in[4];  // noise [8192]
    float* out = (float*)d_out;                   // spikes [8192]

    pack_x_kernel<<<1, NTHR>>>(x);
    snn_bits_kernel<<<OUT_F, NTHR>>>(states, mem, thr, noise, out);
}